// round 3
// baseline (speedup 1.0000x reference)
#include <cuda_runtime.h>

#define BB 16384
#define CC 8192
#define NUM_TAIL 16
#define NTHREADS 256
#define VEC_PER_THREAD 8   // 8192 floats / 4 (float4) / 256 threads

// Scratch (no cudaMalloc allowed) — device globals.
__device__ int   g_counts[CC];
__device__ float g_lse[BB];
__device__ float g_xtrue[BB];

__device__ __forceinline__ int clamp_lab(int lab) {
    lab = lab < 0 ? 0 : lab;
    return lab >= CC ? CC - 1 : lab;
}

__global__ void zero_counts_kernel() {
    int i = blockIdx.x * blockDim.x + threadIdx.x;
    if (i < CC) g_counts[i] = 0;
}

// One CTA per row: streaming max/argmax + exp-sum in a single HBM pass.
__global__ __launch_bounds__(NTHREADS) void row_kernel(
    const float* __restrict__ x, const int* __restrict__ labels)
{
    const int row = blockIdx.x;
    const int t   = threadIdx.x;
    const float4* xr = reinterpret_cast<const float4*>(x + (size_t)row * CC);

    // Thread 0 fetches x[row, true_label] (row is being streamed by this
    // block anyway; likely L1/L2 hit). Needed later by finalize.
    if (t == 0) {
        int lab = clamp_lab(labels[row]);
        g_xtrue[row] = x[(size_t)row * CC + (size_t)lab];
    }

    // Load this thread's 32 elements into registers (8 x LDG.128).
    float4 v[VEC_PER_THREAD];
#pragma unroll
    for (int i = 0; i < VEC_PER_THREAD; i++)
        v[i] = xr[i * NTHREADS + t];

    // Local max + argmax. Column of v[i] component j is (i*256+t)*4 + j,
    // ascending in i and j for fixed t, so strict '>' keeps first occurrence.
    float m = -3.4e38f;
    int   idx = 0x7fffffff;
#pragma unroll
    for (int i = 0; i < VEC_PER_THREAD; i++) {
        int base = (i * NTHREADS + t) * 4;
        if (v[i].x > m) { m = v[i].x; idx = base;     }
        if (v[i].y > m) { m = v[i].y; idx = base + 1; }
        if (v[i].z > m) { m = v[i].z; idx = base + 2; }
        if (v[i].w > m) { m = v[i].w; idx = base + 3; }
    }

    // Local exp-sum against local max.
    float s = 0.f;
#pragma unroll
    for (int i = 0; i < VEC_PER_THREAD; i++) {
        s += __expf(v[i].x - m);
        s += __expf(v[i].y - m);
        s += __expf(v[i].z - m);
        s += __expf(v[i].w - m);
    }

    // Warp butterfly merge of (m, s, idx) with first-index tie-break.
#pragma unroll
    for (int off = 16; off > 0; off >>= 1) {
        float m2 = __shfl_xor_sync(0xffffffffu, m, off);
        float s2 = __shfl_xor_sync(0xffffffffu, s, off);
        int   i2 = __shfl_xor_sync(0xffffffffu, idx, off);
        float M  = fmaxf(m, m2);
        s = s * __expf(m - M) + s2 * __expf(m2 - M);
        if (m2 > m || (m2 == m && i2 < idx)) idx = i2;
        m = M;
    }

    // Cross-warp merge (8 warps) via shared memory; warp 0 finishes.
    __shared__ float sm[8], ss[8];
    __shared__ int   si[8];
    const int warp = t >> 5, lane = t & 31;
    if (lane == 0) { sm[warp] = m; ss[warp] = s; si[warp] = idx; }
    __syncthreads();
    if (warp == 0) {
        m   = (lane < 8) ? sm[lane] : -3.4e38f;
        s   = (lane < 8) ? ss[lane] : 0.f;
        idx = (lane < 8) ? si[lane] : 0x7fffffff;
#pragma unroll
        for (int off = 16; off > 0; off >>= 1) {
            float m2 = __shfl_xor_sync(0xffffffffu, m, off);
            float s2 = __shfl_xor_sync(0xffffffffu, s, off);
            int   i2 = __shfl_xor_sync(0xffffffffu, idx, off);
            float M  = fmaxf(m, m2);
            s = s * __expf(m - M) + s2 * __expf(m2 - M);
            if (m2 > m || (m2 == m && i2 < idx)) idx = i2;
            m = M;
        }
        if (lane == 0) {
            g_lse[row] = m + __logf(s);
            atomicAdd(&g_counts[idx], 1);
        }
    }
}

// Per-sample weights + focal penalty + deterministic tree reduction.
// is_tail is computed from the label directly (tail_mask = arange(C) >= C-16
// by construction in the reference), avoiding any mask-dtype ambiguity.
__global__ __launch_bounds__(1024) void finalize_kernel(
    const int* __restrict__ labels,
    const int* __restrict__ prev,
    float* __restrict__ out)
{
    const int t = threadIdx.x;
    float acc = 0.f;
    for (int r = t; r < BB; r += 1024) {
        int lab = clamp_lab(labels[r]);
        float p = __expf(g_xtrue[r] - g_lse[r]);   // softmax prob of true class
        float w = 1.f;
        if (lab >= CC - NUM_TAIL) {
            int pv = prev[lab];
            int cu = g_counts[lab];
            if      (pv > 0 && cu < pv) w = 4.f;
            else if (pv > 0 && cu > pv) w = 2.f;
            else                        w = 3.f;
        }
        acc += -__logf(p + 1e-7f) * (1.f - p) * w;
    }
    __shared__ float red[32];
#pragma unroll
    for (int off = 16; off > 0; off >>= 1)
        acc += __shfl_xor_sync(0xffffffffu, acc, off);
    if ((t & 31) == 0) red[t >> 5] = acc;
    __syncthreads();
    if (t < 32) {
        acc = red[t];
#pragma unroll
        for (int off = 16; off > 0; off >>= 1)
            acc += __shfl_xor_sync(0xffffffffu, acc, off);
        if (t == 0) out[0] = acc * (0.1f / (float)BB);
    }
}

extern "C" void kernel_launch(void* const* d_in, const int* in_sizes, int n_in,
                              void* d_out, int out_size)
{
    const float* x      = (const float*)d_in[0];
    const int*   labels = (const int*)d_in[1];
    const int*   prev   = (const int*)d_in[2];
    float*       out    = (float*)d_out;

    zero_counts_kernel<<<CC / 256, 256>>>();
    row_kernel<<<BB, NTHREADS>>>(x, labels);
    finalize_kernel<<<1, 1024>>>(labels, prev, out);
}

// round 4
// speedup vs baseline: 1.0208x; 1.0208x over previous
#include <cuda_runtime.h>

#define BB 16384
#define CC 8192
#define NUM_TAIL 16
#define NTHREADS 512
#define VEC_PER_THREAD 4   // 8192 floats / 4 (float4) / 512 threads

// Scratch (no cudaMalloc allowed) — device globals. Static-zero initialized;
// finalize_kernel re-zeroes g_counts after use so every graph replay starts clean.
__device__ int   g_counts[CC];
__device__ float g_lse[BB];
__device__ float g_xtrue[BB];

__device__ __forceinline__ int clamp_lab(int lab) {
    lab = lab < 0 ? 0 : lab;
    return lab >= CC ? CC - 1 : lab;
}

// One CTA per row: streaming max/argmax + exp-sum in a single HBM pass.
__global__ __launch_bounds__(NTHREADS) void row_kernel(
    const float* __restrict__ x, const int* __restrict__ labels)
{
    const int row = blockIdx.x;
    const int t   = threadIdx.x;
    const float4* xr = reinterpret_cast<const float4*>(x + (size_t)row * CC);

    const int lab = clamp_lab(labels[row]);

    // Load this thread's 16 elements into registers (4 x LDG.128).
    float4 v[VEC_PER_THREAD];
#pragma unroll
    for (int i = 0; i < VEC_PER_THREAD; i++)
        v[i] = xr[i * NTHREADS + t];

    // The thread owning column `lab` writes x_true from registers (no extra LDG).
    {
        int lv = lab >> 2;                 // float4 index
        int owner_t = lv & (NTHREADS - 1);
        int owner_i = lv >> 9;             // / NTHREADS
        if (t == owner_t) {
            float4 vv = v[owner_i];
            int c = lab & 3;
            float val = (c == 0) ? vv.x : (c == 1) ? vv.y : (c == 2) ? vv.z : vv.w;
            g_xtrue[row] = val;
        }
    }

    // Local max + argmax. Column of v[i] component j is (i*512+t)*4 + j,
    // ascending in i and j for fixed t, so strict '>' keeps first occurrence.
    float m = -3.4e38f;
    int   idx = 0x7fffffff;
#pragma unroll
    for (int i = 0; i < VEC_PER_THREAD; i++) {
        int base = (i * NTHREADS + t) * 4;
        if (v[i].x > m) { m = v[i].x; idx = base;     }
        if (v[i].y > m) { m = v[i].y; idx = base + 1; }
        if (v[i].z > m) { m = v[i].z; idx = base + 2; }
        if (v[i].w > m) { m = v[i].w; idx = base + 3; }
    }

    // Local exp-sum against local max.
    float s = 0.f;
#pragma unroll
    for (int i = 0; i < VEC_PER_THREAD; i++) {
        s += __expf(v[i].x - m);
        s += __expf(v[i].y - m);
        s += __expf(v[i].z - m);
        s += __expf(v[i].w - m);
    }

    // Warp butterfly merge of (m, s, idx) with first-index tie-break.
#pragma unroll
    for (int off = 16; off > 0; off >>= 1) {
        float m2 = __shfl_xor_sync(0xffffffffu, m, off);
        float s2 = __shfl_xor_sync(0xffffffffu, s, off);
        int   i2 = __shfl_xor_sync(0xffffffffu, idx, off);
        float M  = fmaxf(m, m2);
        s = s * __expf(m - M) + s2 * __expf(m2 - M);
        if (m2 > m || (m2 == m && i2 < idx)) idx = i2;
        m = M;
    }

    // Cross-warp merge (16 warps) via shared memory; warp 0 finishes.
    __shared__ float sm[16], ss[16];
    __shared__ int   si[16];
    const int warp = t >> 5, lane = t & 31;
    if (lane == 0) { sm[warp] = m; ss[warp] = s; si[warp] = idx; }
    __syncthreads();
    if (warp == 0) {
        m   = (lane < 16) ? sm[lane] : -3.4e38f;
        s   = (lane < 16) ? ss[lane] : 0.f;
        idx = (lane < 16) ? si[lane] : 0x7fffffff;
#pragma unroll
        for (int off = 16; off > 0; off >>= 1) {
            float m2 = __shfl_xor_sync(0xffffffffu, m, off);
            float s2 = __shfl_xor_sync(0xffffffffu, s, off);
            int   i2 = __shfl_xor_sync(0xffffffffu, idx, off);
            float M  = fmaxf(m, m2);
            s = s * __expf(m - M) + s2 * __expf(m2 - M);
            if (m2 > m || (m2 == m && i2 < idx)) idx = i2;
            m = M;
        }
        if (lane == 0) {
            g_lse[row] = m + __logf(s);
            atomicAdd(&g_counts[idx], 1);
        }
    }
}

// Per-sample weights + focal penalty + deterministic tree reduction.
// is_tail computed from the label directly (tail_mask = arange(C) >= C-16 by
// construction). Also re-zeroes g_counts after use for the next graph replay.
__global__ __launch_bounds__(1024) void finalize_kernel(
    const int* __restrict__ labels,
    const int* __restrict__ prev,
    float* __restrict__ out)
{
    const int t = threadIdx.x;
    float acc = 0.f;
    for (int r = t; r < BB; r += 1024) {
        int lab = clamp_lab(labels[r]);
        float p = __expf(g_xtrue[r] - g_lse[r]);   // softmax prob of true class
        float w = 1.f;
        if (lab >= CC - NUM_TAIL) {
            int pv = prev[lab];
            int cu = g_counts[lab];
            if      (pv > 0 && cu < pv) w = 4.f;
            else if (pv > 0 && cu > pv) w = 2.f;
            else                        w = 3.f;
        }
        acc += -__logf(p + 1e-7f) * (1.f - p) * w;
    }
    __shared__ float red[32];
#pragma unroll
    for (int off = 16; off > 0; off >>= 1)
        acc += __shfl_xor_sync(0xffffffffu, acc, off);
    if ((t & 31) == 0) red[t >> 5] = acc;
    __syncthreads();

    // All count reads are done (barrier above) — zero for the next replay.
    for (int i = t; i < CC; i += 1024) g_counts[i] = 0;

    if (t < 32) {
        acc = red[t];
#pragma unroll
        for (int off = 16; off > 0; off >>= 1)
            acc += __shfl_xor_sync(0xffffffffu, acc, off);
        if (t == 0) out[0] = acc * (0.1f / (float)BB);
    }
}

extern "C" void kernel_launch(void* const* d_in, const int* in_sizes, int n_in,
                              void* d_out, int out_size)
{
    const float* x      = (const float*)d_in[0];
    const int*   labels = (const int*)d_in[1];
    const int*   prev   = (const int*)d_in[2];
    float*       out    = (float*)d_out;

    row_kernel<<<BB, NTHREADS>>>(x, labels);
    finalize_kernel<<<1, 1024>>>(labels, prev, out);
}